// round 2
// baseline (speedup 1.0000x reference)
#include <cuda_runtime.h>
#include <math.h>

#define BSZ   4096
#define FD    768
#define PD    500
#define ZD    300
#define RNUM  10
#define UNUM  10

// Xp row segment offsets (order: t, v, u, rt, rv, ru)
#define T_OFF   0
#define V_OFF   4096
#define U_OFF   8192
#define RT_OFF  12288
#define RV_OFF  53248
#define RU_OFF  94208
#define XP_ROWS 135168
#define M_BASE  24576          // 4096*6 compact rows
#define M_ROWS  24596          // + 20 sample-0 pair rows

// -------------------- static scratch (no allocations allowed) --------------------
__device__ float g_Xp[(size_t)XP_ROWS * PD];   // tanh(proj) for every node   (~270 MB)
__device__ float g_M [(size_t)M_ROWS  * PD];   // packed [t,v,u,S1,S2,S3] + 20 rows
__device__ float g_Z [(size_t)M_ROWS  * ZD];   // g_M @ hg_w^T (no bias)
__device__ float g_F [(size_t)BSZ * 2100];     // feat
__device__ float g_H1[(size_t)BSZ * 800];
__device__ float g_H2[(size_t)BSZ * 200];

// -------------------- generic SGEMM: C = act(A(MxK) @ B(NxK)^T + bias) ----------
#define BM 128
#define BN 64
#define BK 16
#define TM 8
#define TN 4

__global__ __launch_bounds__(256) void sgemm_nt(
    const float* __restrict__ A, const float* __restrict__ B,
    const float* __restrict__ bias, float* __restrict__ C,
    int M, int N, int K, int act)   // act: 0 none, 1 tanh, 2 relu
{
    __shared__ float As[BK][BM];
    __shared__ float Bs[BK][BN];

    const int tx = threadIdx.x;      // 0..15  -> N
    const int ty = threadIdx.y;      // 0..15  -> M
    const int tid = ty * 16 + tx;
    const int m0 = blockIdx.y * BM;
    const int n0 = blockIdx.x * BN;

    float acc[TM][TN];
#pragma unroll
    for (int i = 0; i < TM; i++)
#pragma unroll
        for (int j = 0; j < TN; j++) acc[i][j] = 0.f;

    const int aRow  = tid >> 1;        // 0..127
    const int aCol0 = (tid & 1) * 8;   // 0 or 8
    const int bRow  = tid >> 2;        // 0..63
    const int bCol0 = (tid & 3) * 4;   // 0,4,8,12

    for (int k0 = 0; k0 < K; k0 += BK) {
#pragma unroll
        for (int j = 0; j < 8; j++) {
            int k = k0 + aCol0 + j;
            int m = m0 + aRow;
            As[aCol0 + j][aRow] = (m < M && k < K) ? A[(size_t)m * K + k] : 0.f;
        }
#pragma unroll
        for (int j = 0; j < 4; j++) {
            int k = k0 + bCol0 + j;
            int n = n0 + bRow;
            Bs[bCol0 + j][bRow] = (n < N && k < K) ? B[(size_t)n * K + k] : 0.f;
        }
        __syncthreads();

#pragma unroll
        for (int kk = 0; kk < BK; kk++) {
            float4 a0 = *reinterpret_cast<const float4*>(&As[kk][ty * TM]);
            float4 a1 = *reinterpret_cast<const float4*>(&As[kk][ty * TM + 4]);
            float4 bb = *reinterpret_cast<const float4*>(&Bs[kk][tx * TN]);
            float av[8] = {a0.x, a0.y, a0.z, a0.w, a1.x, a1.y, a1.z, a1.w};
            float bv[4] = {bb.x, bb.y, bb.z, bb.w};
#pragma unroll
            for (int i = 0; i < TM; i++)
#pragma unroll
                for (int j = 0; j < TN; j++)
                    acc[i][j] += av[i] * bv[j];
        }
        __syncthreads();
    }

#pragma unroll
    for (int i = 0; i < TM; i++) {
        int m = m0 + ty * TM + i;
        if (m >= M) continue;
#pragma unroll
        for (int j = 0; j < TN; j++) {
            int n = n0 + tx * TN + j;
            if (n >= N) continue;
            float v = acc[i][j];
            if (bias) v += bias[n];
            if (act == 1)      v = tanhf(v);
            else if (act == 2) v = fmaxf(v, 0.f);
            C[(size_t)m * N + n] = v;
        }
    }
}

// ------------ K2: per-sample group sums over PD dims + pack for hg GEMM ---------
__global__ void reduce_pack(const float* __restrict__ Xp, float* __restrict__ Mo)
{
    int b = blockIdx.x;
    for (int d = threadIdx.x; d < PD; d += blockDim.x) {
        float t = Xp[(size_t)(T_OFF + b) * PD + d];
        float v = Xp[(size_t)(V_OFF + b) * PD + d];
        float u = Xp[(size_t)(U_OFF + b) * PD + d];
        float s1 = 0.f, s2 = 0.f, s3 = 0.f;
#pragma unroll
        for (int i = 0; i < RNUM; i++) s1 += Xp[(size_t)(RT_OFF + b * RNUM + i) * PD + d];
#pragma unroll
        for (int i = 0; i < RNUM; i++) s2 += Xp[(size_t)(RV_OFF + b * RNUM + i) * PD + d];
#pragma unroll
        for (int i = 0; i < UNUM; i++) s3 += Xp[(size_t)(RU_OFF + b * UNUM + i) * PD + d];
        size_t ro = (size_t)b * 6 * PD;
        Mo[ro + 0 * PD + d] = t;
        Mo[ro + 1 * PD + d] = v;
        Mo[ro + 2 * PD + d] = u;
        Mo[ro + 3 * PD + d] = s1;
        Mo[ro + 4 * PD + d] = s2;
        Mo[ro + 5 * PD + d] = s3;
        if (b == 0) {
#pragma unroll
            for (int i = 0; i < RNUM; i++) {
                Mo[(size_t)(M_BASE + i) * PD + d]        = Xp[(size_t)(RT_OFF + i) * PD + d];
                Mo[(size_t)(M_BASE + RNUM + i) * PD + d] = Xp[(size_t)(RV_OFF + i) * PD + d];
            }
        }
    }
}

// ------------ K4: hypergraph closed-form epilogue + feat assembly ---------------
__global__ void epilogue(const float* __restrict__ Z, const float* __restrict__ hg_b,
                         const float* __restrict__ sim, const float* __restrict__ rlabel,
                         const float* __restrict__ lbl_w, const float* __restrict__ lbl_b,
                         float* __restrict__ F)
{
    int b = blockIdx.x;
    __shared__ float sw[RNUM];
    __shared__ float slbl;
    if (threadIdx.x == 0) {
        float mx = -1e30f;
        for (int i = 0; i < RNUM; i++) mx = fmaxf(mx, sim[b * RNUM + i]);
        float s = 0.f;
        for (int i = 0; i < RNUM; i++) { sw[i] = expf(sim[b * RNUM + i] - mx); s += sw[i]; }
        float inv = 1.f / s;
        float la = 0.f;
        for (int i = 0; i < RNUM; i++) { sw[i] *= inv; la += sw[i] * rlabel[b * RNUM + i]; }
        slbl = la;
    }
    __syncthreads();
    float lblagg = slbl;

    for (int d = threadIdx.x; d < ZD; d += blockDim.x) {
        float hb = hg_b[d];
        size_t ro = (size_t)b * 6 * ZD;
        float xt_t = Z[ro + 0 * ZD + d] + hb;
        float xt_v = Z[ro + 1 * ZD + d] + hb;
        float xt_u = Z[ro + 2 * ZD + d] + hb;
        float s1   = Z[ro + 3 * ZD + d] + 10.f * hb;
        float s2   = Z[ro + 4 * ZD + d] + 10.f * hb;
        float s3   = Z[ro + 5 * ZD + d] + 10.f * hb;

        float yg0 = (xt_t + xt_v + xt_u) * (1.f / 3.f);
        float yg1 = (s1 + xt_t) * (1.f / 11.f);
        float yg2 = (s2 + xt_v) * (1.f / 11.f);
        float yg3 = (s3 + xt_u) * (1.f / 11.f);

        float xo0 = fmaxf(0.5f * (yg0 + yg1), 0.f);
        float xo1 = fmaxf(0.5f * (yg0 + yg2), 0.f);
        float xo2 = fmaxf(0.5f * (yg0 + yg3), 0.f);

        float rt_agg, rv_agg;
        if (b == 0) {
            rt_agg = 0.f; rv_agg = 0.f;
#pragma unroll
            for (int i = 0; i < RNUM; i++) {
                float xt_rt = Z[(size_t)(M_BASE + i) * ZD + d] + hb;
                float xt_rv = Z[(size_t)(M_BASE + RNUM + i) * ZD + d] + hb;
                float yp = 0.5f * (xt_rt + xt_rv);
                rt_agg += sw[i] * fmaxf(0.5f * (yg1 + yp), 0.f);
                rv_agg += sw[i] * fmaxf(0.5f * (yg2 + yp), 0.f);
            }
        } else {
            // all retrieved nodes of a sample share the same Xo -> softmax sums to 1
            rt_agg = fmaxf(yg1, 0.f);
            rv_agg = fmaxf(yg2, 0.f);
        }
        float ru_agg = fmaxf(yg3, 0.f);
        float le = fmaxf(lbl_w[d] * lblagg + lbl_b[d], 0.f);

        float* Fr = F + (size_t)b * 2100;
        Fr[          d] = xo0;
        Fr[ 300 +    d] = xo1;
        Fr[ 600 +    d] = xo2;
        Fr[ 900 +    d] = rv_agg;
        Fr[1200 +    d] = rt_agg;
        Fr[1500 +    d] = ru_agg;
        Fr[1800 +    d] = le;
    }
}

// ------------ K7: final 200->1 dot + sigmoid (one warp per row) -----------------
__global__ void final_head(const float* __restrict__ H2, const float* __restrict__ w,
                           const float* __restrict__ b, float* __restrict__ out)
{
    int row  = blockIdx.x * (blockDim.x >> 5) + (threadIdx.x >> 5);
    int lane = threadIdx.x & 31;
    if (row >= BSZ) return;
    float s = 0.f;
    for (int j = lane; j < 200; j += 32) s += H2[(size_t)row * 200 + j] * w[j];
#pragma unroll
    for (int off = 16; off > 0; off >>= 1)
        s += __shfl_xor_sync(0xFFFFFFFFu, s, off);
    if (lane == 0) out[row] = 1.f / (1.f + expf(-(s + b[0])));
}

// -------------------------------- launch ---------------------------------------
static inline dim3 gemm_grid(int M, int N) {
    return dim3((N + BN - 1) / BN, (M + BM - 1) / BM);
}

extern "C" void kernel_launch(void* const* d_in, const int* in_sizes, int n_in,
                              void* d_out, int out_size)
{
    const float* visual  = (const float*)d_in[0];
    const float* textual = (const float*)d_in[1];
    const float* sim     = (const float*)d_in[2];
    const float* rvis    = (const float*)d_in[3];
    const float* rtxt    = (const float*)d_in[4];
    const float* rlabel  = (const float*)d_in[5];
    const float* user    = (const float*)d_in[6];
    const float* ruser   = (const float*)d_in[7];
    // d_in[8] retrieved_user_similarity: mathematically dead (softmax sums to 1)
    const float* vis_w = (const float*)d_in[9],  *vis_b = (const float*)d_in[10];
    const float* txt_w = (const float*)d_in[11], *txt_b = (const float*)d_in[12];
    const float* usr_w = (const float*)d_in[13], *usr_b = (const float*)d_in[14];
    const float* rvis_w = (const float*)d_in[15], *rvis_b = (const float*)d_in[16];
    const float* rtxt_w = (const float*)d_in[17], *rtxt_b = (const float*)d_in[18];
    const float* rusr_w = (const float*)d_in[19], *rusr_b = (const float*)d_in[20];
    const float* hg_w = (const float*)d_in[21], *hg_b = (const float*)d_in[22];
    const float* lbl_w = (const float*)d_in[23], *lbl_b = (const float*)d_in[24];
    const float* p1_w = (const float*)d_in[25], *p1_b = (const float*)d_in[26];
    const float* p2_w = (const float*)d_in[27], *p2_b = (const float*)d_in[28];
    const float* p3_w = (const float*)d_in[29], *p3_b = (const float*)d_in[30];

    float *xp, *mbuf, *z, *f, *h1, *h2;
    cudaGetSymbolAddress((void**)&xp,   g_Xp);
    cudaGetSymbolAddress((void**)&mbuf, g_M);
    cudaGetSymbolAddress((void**)&z,    g_Z);
    cudaGetSymbolAddress((void**)&f,    g_F);
    cudaGetSymbolAddress((void**)&h1,   g_H1);
    cudaGetSymbolAddress((void**)&h2,   g_H2);

    dim3 blk(16, 16);

    // K1: six projection GEMMs + tanh -> Xp segments
    sgemm_nt<<<gemm_grid(BSZ, PD), blk>>>(textual, txt_w, txt_b,
                                          xp + (size_t)T_OFF * PD, BSZ, PD, FD, 1);
    sgemm_nt<<<gemm_grid(BSZ, PD), blk>>>(visual, vis_w, vis_b,
                                          xp + (size_t)V_OFF * PD, BSZ, PD, FD, 1);
    sgemm_nt<<<gemm_grid(BSZ, PD), blk>>>(user, usr_w, usr_b,
                                          xp + (size_t)U_OFF * PD, BSZ, PD, FD, 1);
    sgemm_nt<<<gemm_grid(BSZ * RNUM, PD), blk>>>(rtxt, rtxt_w, rtxt_b,
                                          xp + (size_t)RT_OFF * PD, BSZ * RNUM, PD, FD, 1);
    sgemm_nt<<<gemm_grid(BSZ * RNUM, PD), blk>>>(rvis, rvis_w, rvis_b,
                                          xp + (size_t)RV_OFF * PD, BSZ * RNUM, PD, FD, 1);
    sgemm_nt<<<gemm_grid(BSZ * UNUM, PD), blk>>>(ruser, rusr_w, rusr_b,
                                          xp + (size_t)RU_OFF * PD, BSZ * UNUM, PD, FD, 1);

    // K2: group sums in PD space (hypergraph edge sums commute through hg linear)
    reduce_pack<<<BSZ, 128>>>(xp, mbuf);

    // K3: hg GEMM on compacted 24596 rows (no bias; handled in epilogue)
    sgemm_nt<<<gemm_grid(M_ROWS, ZD), blk>>>(mbuf, hg_w, nullptr, z, M_ROWS, ZD, PD, 0);

    // K4: closed-form hypergraph conv + retrieval aggregation + feat assembly
    epilogue<<<BSZ, 128>>>(z, hg_b, sim, rlabel, lbl_w, lbl_b, f);

    // K5/K6: MLP
    sgemm_nt<<<gemm_grid(BSZ, 800), blk>>>(f,  p1_w, p1_b, h1, BSZ, 800, 2100, 2);
    sgemm_nt<<<gemm_grid(BSZ, 200), blk>>>(h1, p2_w, p2_b, h2, BSZ, 200, 800, 2);

    // K7: sigmoid head
    final_head<<<(BSZ * 32 + 255) / 256, 256>>>(h2, p3_w, p3_b, (float*)d_out);
}

// round 7
// speedup vs baseline: 2.6600x; 2.6600x over previous
#include <cuda_runtime.h>
#include <cuda_bf16.h>
#include <cstdint>
#include <math.h>

#define BSZ   4096
#define FD    768
#define PD    500
#define ZD    300
#define RNUM  10
#define UNUM  10

// Xp row segment offsets (order: t, v, u, rt, rv, ru)
#define T_OFF   0
#define V_OFF   4096
#define U_OFF   8192
#define RT_OFF  12288
#define RV_OFF  53248
#define RU_OFF  94208
#define XP_ROWS 135168
#define M_BASE  24576          // 4096*6 compact rows
#define M_ROWS  24596          // + 20 sample-0 pair rows
#define M_PAD_HG 24704         // 193*128

// bf16 split layout: per row 2*Kpad cols = [hi(Kpad) | lo(Kpad)]
#define AK2 1536               // proj: 2*768

// -------------------- static scratch (no allocations allowed) -------------------
__device__ float g_Xp[(size_t)XP_ROWS * PD];
__device__ __nv_bfloat16 g_Abf[(size_t)XP_ROWS * AK2];     // proj inputs hi|lo
__device__ __nv_bfloat16 g_Bbf[6 * 512 * AK2];             // proj weights hi|lo
__device__ float g_M [(size_t)M_ROWS  * PD];
__device__ __nv_bfloat16 g_hgA[(size_t)M_PAD_HG * 1024];   // hg A hi|lo (Kpad 512)
__device__ __nv_bfloat16 g_hgW[(size_t)384 * 1024];
__device__ float g_Z [(size_t)M_ROWS  * ZD];
__device__ float g_F [(size_t)BSZ * 2100];
__device__ __nv_bfloat16 g_p1A[(size_t)BSZ * 4224];        // p1 A hi|lo (Kpad 2112)
__device__ __nv_bfloat16 g_p1W[(size_t)896 * 4224];
__device__ float g_H1[(size_t)BSZ * 800];
__device__ float g_H2[(size_t)BSZ * 200];

// ============================ PTX helpers =======================================
__device__ __forceinline__ uint32_t smem_u32(const void* p) {
    uint32_t a;
    asm("{ .reg .u64 t; cvta.to.shared.u64 t, %1; cvt.u32.u64 %0, t; }" : "=r"(a) : "l"(p));
    return a;
}
__device__ __forceinline__ void cp16(uint32_t dst, const void* src) {
    asm volatile("cp.async.cg.shared.global [%0], [%1], 16;" :: "r"(dst), "l"(src));
}
#define CP_COMMIT() asm volatile("cp.async.commit_group;" ::: "memory")
#define CP_WAIT0()  asm volatile("cp.async.wait_group 0;" ::: "memory")
#define CP_WAIT1()  asm volatile("cp.async.wait_group 1;" ::: "memory")

__device__ __forceinline__ void ldsm_x4(uint32_t& r0, uint32_t& r1, uint32_t& r2, uint32_t& r3,
                                        uint32_t addr) {
    asm volatile("ldmatrix.sync.aligned.m8n8.x4.shared.b16 {%0,%1,%2,%3}, [%4];"
                 : "=r"(r0), "=r"(r1), "=r"(r2), "=r"(r3) : "r"(addr));
}
__device__ __forceinline__ void mma16816(float* d, const uint32_t* a, const uint32_t* b) {
    asm volatile("mma.sync.aligned.m16n8k16.row.col.f32.bf16.bf16.f32 "
                 "{%0,%1,%2,%3}, {%4,%5,%6,%7}, {%8,%9}, {%0,%1,%2,%3};"
                 : "+f"(d[0]), "+f"(d[1]), "+f"(d[2]), "+f"(d[3])
                 : "r"(a[0]), "r"(a[1]), "r"(a[2]), "r"(a[3]), "r"(b[0]), "r"(b[1]));
}
#define SWZ128(b)  ((b) ^ (((b) >> 3) & 0x70))

// ======================= bf16 split conversion kernels ==========================
__global__ void conv_hilo(const float* __restrict__ src, __nv_bfloat16* __restrict__ dst,
                          int nrows)   // src [nrows x 768] -> dst [nrows x 1536] hi|lo
{
    int i = blockIdx.x * blockDim.x + threadIdx.x;
    int total = nrows * (FD / 4);
    if (i >= total) return;
    int row = i / (FD / 4), c4 = (i % (FD / 4)) * 4;
    float4 x = *reinterpret_cast<const float4*>(src + (size_t)row * FD + c4);
    __nv_bfloat16 h0 = __float2bfloat16(x.x), h1 = __float2bfloat16(x.y);
    __nv_bfloat16 h2 = __float2bfloat16(x.z), h3 = __float2bfloat16(x.w);
    __nv_bfloat16 l0 = __float2bfloat16(x.x - __bfloat162float(h0));
    __nv_bfloat16 l1 = __float2bfloat16(x.y - __bfloat162float(h1));
    __nv_bfloat16 l2 = __float2bfloat16(x.z - __bfloat162float(h2));
    __nv_bfloat16 l3 = __float2bfloat16(x.w - __bfloat162float(h3));
    __nv_bfloat16* dh = dst + (size_t)row * AK2 + c4;
    __nv_bfloat16* dl = dh + FD;
    dh[0] = h0; dh[1] = h1; dh[2] = h2; dh[3] = h3;
    dl[0] = l0; dl[1] = l1; dl[2] = l2; dl[3] = l3;
}

__global__ void conv_w(const float* __restrict__ w, __nv_bfloat16* __restrict__ dst)
{   // w [500 x 768] -> dst [512 x 1536] hi|lo, rows >= 500 zeroed
    int i = blockIdx.x * blockDim.x + threadIdx.x;
    if (i >= 512 * FD) return;
    int row = i / FD, col = i % FD;
    float x = (row < PD) ? w[(size_t)row * FD + col] : 0.f;
    __nv_bfloat16 h = __float2bfloat16(x);
    __nv_bfloat16 l = __float2bfloat16(x - __bfloat162float(h));
    dst[(size_t)row * AK2 + col] = h;
    dst[(size_t)row * AK2 + FD + col] = l;
}

// generic: float [rows_src x Kreal] -> bf16 [rows_dst x 2*Kpad] hi|lo, zero padded
__global__ void conv_split(const float* __restrict__ src, __nv_bfloat16* __restrict__ dst,
                           int rows_src, int Kreal, int Kpad, long long total)
{
    long long i = (long long)blockIdx.x * blockDim.x + threadIdx.x;
    if (i >= total) return;
    int col = (int)(i % Kpad);
    long long row = i / Kpad;
    float x = (row < rows_src && col < Kreal) ? src[row * Kreal + col] : 0.f;
    __nv_bfloat16 h = __float2bfloat16(x);
    __nv_bfloat16 l = __float2bfloat16(x - __bfloat162float(h));
    dst[row * (2 * (long long)Kpad) + col] = h;
    dst[row * (2 * (long long)Kpad) + Kpad + col] = l;
}

// =================== HMMA GEMM: C = act(A @ B^T + bias), 3-term bf16 split ======
// A [Mpad x 2*Kpad] hi|lo, B [Npad x 2*Kpad] hi|lo, C [M x Nreal] fp32.
// CTA 128x128, 8 warps (2x4), warp tile 64x32, K chunk 64 bf16, double buffered.
#define SM_BUF 32768

__device__ __forceinline__ void load_chunk(
    const __nv_bfloat16* __restrict__ A, const __nv_bfloat16* __restrict__ B,
    int m0, int n0, int strideK, int a_off, int b_off, uint32_t sbase, int tid)
{
#pragma unroll
    for (int i = 0; i < 4; i++) {          // A: 128 rows x 128B
        int u = tid + i * 256;
        int r = u >> 3, q = u & 7;
        cp16(sbase + SWZ128(r * 128 + q * 16),
             A + (size_t)(m0 + r) * strideK + a_off + q * 8);
    }
#pragma unroll
    for (int i = 0; i < 4; i++) {          // B: 128 rows x 128B
        int u = tid + i * 256;
        int r = u >> 3, q = u & 7;
        cp16(sbase + 16384 + SWZ128(r * 128 + q * 16),
             B + (size_t)(n0 + r) * strideK + b_off + q * 8);
    }
}

__global__ __launch_bounds__(256) void mma_gemm(
    const __nv_bfloat16* __restrict__ A, const __nv_bfloat16* __restrict__ B,
    const float* __restrict__ bias, float* __restrict__ C,
    int M, int Nreal, int Kpad, int act)   // act: 0 none, 1 tanh, 2 relu
{
    extern __shared__ char smem[];
    const uint32_t sb = smem_u32(smem);
    const int tid = threadIdx.x, lane = tid & 31, wid = tid >> 5;
    const int warp_m = wid >> 2, warp_n = wid & 3;
    const int m0 = blockIdx.y * 128, n0 = blockIdx.x * 128;
    const int strideK = 2 * Kpad;
    const int kc = Kpad >> 6;
    const int nchunk = 3 * kc;

    float acc[4][4][4];
#pragma unroll
    for (int i = 0; i < 4; i++)
#pragma unroll
        for (int j = 0; j < 4; j++)
#pragma unroll
            for (int k = 0; k < 4; k++) acc[i][j][k] = 0.f;

    // chunk c: seg 0: A hi * B hi; seg 1: A hi * B lo; seg 2: A lo * B hi
    load_chunk(A, B, m0, n0, strideK, 0, 0, sb, tid);
    CP_COMMIT();

    int seg = 0, s = 0;
    for (int c = 0; c < nchunk; c++) {
        int cn = c + 1;
        if (cn < nchunk) {
            int sn = s + 1, segn = seg;
            if (sn == kc) { sn = 0; segn = seg + 1; }
            int ao = ((segn == 2) ? Kpad : 0) + sn * 64;
            int bo = ((segn == 1) ? Kpad : 0) + sn * 64;
            load_chunk(A, B, m0, n0, strideK, ao, bo, sb + (cn & 1) * SM_BUF, tid);
            CP_COMMIT();
            CP_WAIT1();
        } else {
            CP_WAIT0();
        }
        __syncthreads();

        const uint32_t base = sb + (c & 1) * SM_BUF;
#pragma unroll
        for (int ks = 0; ks < 4; ks++) {
            uint32_t a[4][4], b[2][4];
#pragma unroll
            for (int mt = 0; mt < 4; mt++) {
                int row = warp_m * 64 + mt * 16 + (lane & 15);
                int byo = row * 128 + ks * 32 + ((lane >> 4) & 1) * 16;
                ldsm_x4(a[mt][0], a[mt][1], a[mt][2], a[mt][3], base + SWZ128(byo));
            }
#pragma unroll
            for (int np = 0; np < 2; np++) {
                int nrow = warp_n * 32 + np * 16 + ((lane >> 4) & 1) * 8 + (lane & 7);
                int byo = nrow * 128 + ks * 32 + ((lane >> 3) & 1) * 16;
                ldsm_x4(b[np][0], b[np][1], b[np][2], b[np][3],
                        base + 16384 + SWZ128(byo));
            }
#pragma unroll
            for (int mt = 0; mt < 4; mt++)
#pragma unroll
                for (int nt = 0; nt < 4; nt++)
                    mma16816(acc[mt][nt], a[mt], &b[nt >> 1][(nt & 1) * 2]);
        }
        __syncthreads();
        s++;
        if (s == kc) { s = 0; seg++; }
    }

    // epilogue
#pragma unroll
    for (int mt = 0; mt < 4; mt++) {
        int r0 = m0 + warp_m * 64 + mt * 16 + (lane >> 2);
#pragma unroll
        for (int nt = 0; nt < 4; nt++) {
            int c0 = n0 + warp_n * 32 + nt * 8 + (lane & 3) * 2;
#pragma unroll
            for (int q = 0; q < 4; q++) {
                int r = r0 + ((q >> 1) ? 8 : 0);
                int cc = c0 + (q & 1);
                if (r < M && cc < Nreal) {
                    float v = acc[mt][nt][q];
                    if (bias) v += bias[cc];
                    if (act == 1)      v = tanhf(v);
                    else if (act == 2) v = fmaxf(v, 0.f);
                    C[(size_t)r * Nreal + cc] = v;
                }
            }
        }
    }
}

// -------------------- fp32 SGEMM (p2 only) --------------------------------------
#define BM 128
#define BN 64
#define BK 16
#define TM 8
#define TN 4

__global__ __launch_bounds__(256) void sgemm_nt(
    const float* __restrict__ A, const float* __restrict__ B,
    const float* __restrict__ bias, float* __restrict__ C,
    int M, int N, int K, int act)
{
    __shared__ float As[BK][BM];
    __shared__ float Bs[BK][BN];
    const int tx = threadIdx.x, ty = threadIdx.y;
    const int tid = ty * 16 + tx;
    const int m0 = blockIdx.y * BM, n0 = blockIdx.x * BN;

    float acc[TM][TN];
#pragma unroll
    for (int i = 0; i < TM; i++)
#pragma unroll
        for (int j = 0; j < TN; j++) acc[i][j] = 0.f;

    const int aRow = tid >> 1, aCol0 = (tid & 1) * 8;
    const int bRow = tid >> 2, bCol0 = (tid & 3) * 4;

    for (int k0 = 0; k0 < K; k0 += BK) {
#pragma unroll
        for (int j = 0; j < 8; j++) {
            int k = k0 + aCol0 + j, m = m0 + aRow;
            As[aCol0 + j][aRow] = (m < M && k < K) ? A[(size_t)m * K + k] : 0.f;
        }
#pragma unroll
        for (int j = 0; j < 4; j++) {
            int k = k0 + bCol0 + j, n = n0 + bRow;
            Bs[bCol0 + j][bRow] = (n < N && k < K) ? B[(size_t)n * K + k] : 0.f;
        }
        __syncthreads();
#pragma unroll
        for (int kk = 0; kk < BK; kk++) {
            float4 a0 = *reinterpret_cast<const float4*>(&As[kk][ty * TM]);
            float4 a1 = *reinterpret_cast<const float4*>(&As[kk][ty * TM + 4]);
            float4 bb = *reinterpret_cast<const float4*>(&Bs[kk][tx * TN]);
            float av[8] = {a0.x, a0.y, a0.z, a0.w, a1.x, a1.y, a1.z, a1.w};
            float bv[4] = {bb.x, bb.y, bb.z, bb.w};
#pragma unroll
            for (int i = 0; i < TM; i++)
#pragma unroll
                for (int j = 0; j < TN; j++)
                    acc[i][j] += av[i] * bv[j];
        }
        __syncthreads();
    }
#pragma unroll
    for (int i = 0; i < TM; i++) {
        int m = m0 + ty * TM + i;
        if (m >= M) continue;
#pragma unroll
        for (int j = 0; j < TN; j++) {
            int n = n0 + tx * TN + j;
            if (n >= N) continue;
            float v = acc[i][j];
            if (bias) v += bias[n];
            if (act == 1)      v = tanhf(v);
            else if (act == 2) v = fmaxf(v, 0.f);
            C[(size_t)m * N + n] = v;
        }
    }
}

// ------------ K2: per-sample group sums over PD dims + pack for hg GEMM ---------
__global__ void reduce_pack(const float* __restrict__ Xp, float* __restrict__ Mo)
{
    int b = blockIdx.x;
    for (int d = threadIdx.x; d < PD; d += blockDim.x) {
        float t = Xp[(size_t)(T_OFF + b) * PD + d];
        float v = Xp[(size_t)(V_OFF + b) * PD + d];
        float u = Xp[(size_t)(U_OFF + b) * PD + d];
        float s1 = 0.f, s2 = 0.f, s3 = 0.f;
#pragma unroll
        for (int i = 0; i < RNUM; i++) s1 += Xp[(size_t)(RT_OFF + b * RNUM + i) * PD + d];
#pragma unroll
        for (int i = 0; i < RNUM; i++) s2 += Xp[(size_t)(RV_OFF + b * RNUM + i) * PD + d];
#pragma unroll
        for (int i = 0; i < UNUM; i++) s3 += Xp[(size_t)(RU_OFF + b * UNUM + i) * PD + d];
        size_t ro = (size_t)b * 6 * PD;
        Mo[ro + 0 * PD + d] = t;
        Mo[ro + 1 * PD + d] = v;
        Mo[ro + 2 * PD + d] = u;
        Mo[ro + 3 * PD + d] = s1;
        Mo[ro + 4 * PD + d] = s2;
        Mo[ro + 5 * PD + d] = s3;
        if (b == 0) {
#pragma unroll
            for (int i = 0; i < RNUM; i++) {
                Mo[(size_t)(M_BASE + i) * PD + d]        = Xp[(size_t)(RT_OFF + i) * PD + d];
                Mo[(size_t)(M_BASE + RNUM + i) * PD + d] = Xp[(size_t)(RV_OFF + i) * PD + d];
            }
        }
    }
}

// ------------ K4: hypergraph closed-form epilogue + feat assembly ---------------
__global__ void epilogue(const float* __restrict__ Z, const float* __restrict__ hg_b,
                         const float* __restrict__ sim, const float* __restrict__ rlabel,
                         const float* __restrict__ lbl_w, const float* __restrict__ lbl_b,
                         float* __restrict__ F)
{
    int b = blockIdx.x;
    __shared__ float sw[RNUM];
    __shared__ float slbl;
    if (threadIdx.x == 0) {
        float mx = -1e30f;
        for (int i = 0; i < RNUM; i++) mx = fmaxf(mx, sim[b * RNUM + i]);
        float s = 0.f;
        for (int i = 0; i < RNUM; i++) { sw[i] = expf(sim[b * RNUM + i] - mx); s += sw[i]; }
        float inv = 1.f / s;
        float la = 0.f;
        for (int i = 0; i < RNUM; i++) { sw[i] *= inv; la += sw[i] * rlabel[b * RNUM + i]; }
        slbl = la;
    }
    __syncthreads();
    float lblagg = slbl;

    for (int d = threadIdx.x; d < ZD; d += blockDim.x) {
        float hb = hg_b[d];
        size_t ro = (size_t)b * 6 * ZD;
        float xt_t = Z[ro + 0 * ZD + d] + hb;
        float xt_v = Z[ro + 1 * ZD + d] + hb;
        float xt_u = Z[ro + 2 * ZD + d] + hb;
        float s1   = Z[ro + 3 * ZD + d] + 10.f * hb;
        float s2   = Z[ro + 4 * ZD + d] + 10.f * hb;
        float s3   = Z[ro + 5 * ZD + d] + 10.f * hb;

        float yg0 = (xt_t + xt_v + xt_u) * (1.f / 3.f);
        float yg1 = (s1 + xt_t) * (1.f / 11.f);
        float yg2 = (s2 + xt_v) * (1.f / 11.f);
        float yg3 = (s3 + xt_u) * (1.f / 11.f);

        float xo0 = fmaxf(0.5f * (yg0 + yg1), 0.f);
        float xo1 = fmaxf(0.5f * (yg0 + yg2), 0.f);
        float xo2 = fmaxf(0.5f * (yg0 + yg3), 0.f);

        float rt_agg, rv_agg;
        if (b == 0) {
            rt_agg = 0.f; rv_agg = 0.f;
#pragma unroll
            for (int i = 0; i < RNUM; i++) {
                float xt_rt = Z[(size_t)(M_BASE + i) * ZD + d] + hb;
                float xt_rv = Z[(size_t)(M_BASE + RNUM + i) * ZD + d] + hb;
                float yp = 0.5f * (xt_rt + xt_rv);
                rt_agg += sw[i] * fmaxf(0.5f * (yg1 + yp), 0.f);
                rv_agg += sw[i] * fmaxf(0.5f * (yg2 + yp), 0.f);
            }
        } else {
            rt_agg = fmaxf(yg1, 0.f);
            rv_agg = fmaxf(yg2, 0.f);
        }
        float ru_agg = fmaxf(yg3, 0.f);
        float le = fmaxf(lbl_w[d] * lblagg + lbl_b[d], 0.f);

        float* Fr = F + (size_t)b * 2100;
        Fr[          d] = xo0;
        Fr[ 300 +    d] = xo1;
        Fr[ 600 +    d] = xo2;
        Fr[ 900 +    d] = rv_agg;
        Fr[1200 +    d] = rt_agg;
        Fr[1500 +    d] = ru_agg;
        Fr[1800 +    d] = le;
    }
}

// ------------ K7: final 200->1 dot + sigmoid (one warp per row) -----------------
__global__ void final_head(const float* __restrict__ H2, const float* __restrict__ w,
                           const float* __restrict__ b, float* __restrict__ out)
{
    int row  = blockIdx.x * (blockDim.x >> 5) + (threadIdx.x >> 5);
    int lane = threadIdx.x & 31;
    if (row >= BSZ) return;
    float s = 0.f;
    for (int j = lane; j < 200; j += 32) s += H2[(size_t)row * 200 + j] * w[j];
#pragma unroll
    for (int off = 16; off > 0; off >>= 1)
        s += __shfl_xor_sync(0xFFFFFFFFu, s, off);
    if (lane == 0) out[row] = 1.f / (1.f + expf(-(s + b[0])));
}

// -------------------------------- launch ---------------------------------------
extern "C" void kernel_launch(void* const* d_in, const int* in_sizes, int n_in,
                              void* d_out, int out_size)
{
    const float* visual  = (const float*)d_in[0];
    const float* textual = (const float*)d_in[1];
    const float* sim     = (const float*)d_in[2];
    const float* rvis    = (const float*)d_in[3];
    const float* rtxt    = (const float*)d_in[4];
    const float* rlabel  = (const float*)d_in[5];
    const float* user    = (const float*)d_in[6];
    const float* ruser   = (const float*)d_in[7];
    const float* vis_w = (const float*)d_in[9],  *vis_b = (const float*)d_in[10];
    const float* txt_w = (const float*)d_in[11], *txt_b = (const float*)d_in[12];
    const float* usr_w = (const float*)d_in[13], *usr_b = (const float*)d_in[14];
    const float* rvis_w = (const float*)d_in[15], *rvis_b = (const float*)d_in[16];
    const float* rtxt_w = (const float*)d_in[17], *rtxt_b = (const float*)d_in[18];
    const float* rusr_w = (const float*)d_in[19], *rusr_b = (const float*)d_in[20];
    const float* hg_w = (const float*)d_in[21], *hg_b = (const float*)d_in[22];
    const float* lbl_w = (const float*)d_in[23], *lbl_b = (const float*)d_in[24];
    const float* p1_w = (const float*)d_in[25], *p1_b = (const float*)d_in[26];
    const float* p2_w = (const float*)d_in[27], *p2_b = (const float*)d_in[28];
    const float* p3_w = (const float*)d_in[29], *p3_b = (const float*)d_in[30];

    float *xp, *mbuf, *z, *f, *h1, *h2;
    __nv_bfloat16 *abf, *bbf, *hgA, *hgW, *p1A, *p1W;
    cudaGetSymbolAddress((void**)&xp,   g_Xp);
    cudaGetSymbolAddress((void**)&abf,  g_Abf);
    cudaGetSymbolAddress((void**)&bbf,  g_Bbf);
    cudaGetSymbolAddress((void**)&mbuf, g_M);
    cudaGetSymbolAddress((void**)&hgA,  g_hgA);
    cudaGetSymbolAddress((void**)&hgW,  g_hgW);
    cudaGetSymbolAddress((void**)&z,    g_Z);
    cudaGetSymbolAddress((void**)&f,    g_F);
    cudaGetSymbolAddress((void**)&p1A,  g_p1A);
    cudaGetSymbolAddress((void**)&p1W,  g_p1W);
    cudaGetSymbolAddress((void**)&h1,   g_H1);
    cudaGetSymbolAddress((void**)&h2,   g_H2);

    cudaFuncSetAttribute(mma_gemm, cudaFuncAttributeMaxDynamicSharedMemorySize, 2 * SM_BUF);

    const int CT = 256;
    // ---- convert proj inputs to bf16 hi|lo ----
    auto cvA = [&](const float* src, int doff, int rows) {
        int tot = rows * (FD / 4);
        conv_hilo<<<(tot + CT - 1) / CT, CT>>>(src, abf + (size_t)doff * AK2, rows);
    };
    cvA(textual, T_OFF,  BSZ);
    cvA(visual,  V_OFF,  BSZ);
    cvA(user,    U_OFF,  BSZ);
    cvA(rtxt,    RT_OFF, BSZ * RNUM);
    cvA(rvis,    RV_OFF, BSZ * RNUM);
    cvA(ruser,   RU_OFF, BSZ * UNUM);

    // ---- convert proj weights ----
    const float* ws[6] = {txt_w, vis_w, usr_w, rtxt_w, rvis_w, rusr_w};
    for (int i = 0; i < 6; i++)
        conv_w<<<(512 * FD + CT - 1) / CT, CT>>>(ws[i], bbf + (size_t)i * 512 * AK2);

    // ---- convert hg / p1 weights (independent of activations) ----
    {
        long long tot = (long long)384 * 512;
        conv_split<<<(unsigned)((tot + CT - 1) / CT), CT>>>(hg_w, hgW, ZD, PD, 512, tot);
        tot = (long long)896 * 2112;
        conv_split<<<(unsigned)((tot + CT - 1) / CT), CT>>>(p1_w, p1W, 800, 2100, 2112, tot);
    }

    // ---- projection GEMMs + tanh (HMMA, K'=3*768) ----
    const float* bs[6] = {txt_b, vis_b, usr_b, rtxt_b, rvis_b, rusr_b};
    const int offs[6] = {T_OFF, V_OFF, U_OFF, RT_OFF, RV_OFF, RU_OFF};
    const int rows[6] = {BSZ, BSZ, BSZ, BSZ * RNUM, BSZ * RNUM, BSZ * UNUM};
    for (int i = 0; i < 6; i++) {
        dim3 g(4, rows[i] / 128);   // Npad 512
        mma_gemm<<<g, 256, 2 * SM_BUF>>>(abf + (size_t)offs[i] * AK2,
                                         bbf + (size_t)i * 512 * AK2,
                                         bs[i], xp + (size_t)offs[i] * PD,
                                         rows[i], PD, FD, 1);
    }

    // K2: group sums in PD space
    reduce_pack<<<BSZ, 128>>>(xp, mbuf);

    // conv hg A, then hg GEMM (act none, bias in epilogue)
    {
        long long tot = (long long)M_PAD_HG * 512;
        conv_split<<<(unsigned)((tot + CT - 1) / CT), CT>>>(mbuf, hgA, M_ROWS, PD, 512, tot);
        dim3 g(3, M_PAD_HG / 128);  // Npad 384
        mma_gemm<<<g, 256, 2 * SM_BUF>>>(hgA, hgW, nullptr, z, M_ROWS, ZD, 512, 0);
    }

    // K4: closed-form hypergraph conv + feat assembly
    epilogue<<<BSZ, 128>>>(z, hg_b, sim, rlabel, lbl_w, lbl_b, f);

    // conv p1 A, then p1 GEMM + relu
    {
        long long tot = (long long)BSZ * 2112;
        conv_split<<<(unsigned)((tot + CT - 1) / CT), CT>>>(f, p1A, BSZ, 2100, 2112, tot);
        dim3 g(7, BSZ / 128);       // Npad 896
        mma_gemm<<<g, 256, 2 * SM_BUF>>>(p1A, p1W, p1_b, h1, BSZ, 800, 2112, 2);
    }

    // p2 (small) on fp32 SGEMM
    {
        dim3 blk(16, 16);
        dim3 g((200 + BN - 1) / BN, (BSZ + BM - 1) / BM);
        sgemm_nt<<<g, blk>>>(h1, p2_w, p2_b, h2, BSZ, 200, 800, 2);
    }

    // K7: sigmoid head
    final_head<<<(BSZ * 32 + 255) / 256, 256>>>(h2, p3_w, p3_b, (float*)d_out);
}

// round 8
// speedup vs baseline: 4.4739x; 1.6819x over previous
#include <cuda_runtime.h>
#include <cuda_bf16.h>
#include <cstdint>
#include <math.h>

#define BSZ   4096
#define FD    768
#define PD    500
#define ZD    300
#define RNUM  10
#define UNUM  10

// A segment row offsets (order: t, v, u, rt, rv, ru)
#define T_OFF   0
#define V_OFF   4096
#define U_OFF   8192
#define RT_OFF  12288
#define RV_OFF  53248
#define RU_OFF  94208
#define XP_ROWS 135168
#define M_BASE  24576          // 4096*6 compact rows
#define M_ROWS  24596          // + 20 sample-0 pair rows
#define M_PAD_HG 24704         // 193*128

// -------------------- static scratch (no allocations allowed) -------------------
__device__ __nv_bfloat16 g_Abf[(size_t)XP_ROWS * FD];      // proj inputs, bf16 hi only
__device__ __nv_bfloat16 g_Bbf[6 * 512 * 1536];            // proj weights hi|lo
__device__ float g_M [(size_t)M_ROWS  * PD];               // group-summed tanh outputs
__device__ __nv_bfloat16 g_hgA[(size_t)M_PAD_HG * 512];    // hg A bf16 (Kpad 512)
__device__ __nv_bfloat16 g_hgW[(size_t)384 * 1024];        // hg W hi|lo
__device__ float g_Z  [(size_t)M_ROWS  * ZD];
__device__ __nv_bfloat16 g_p1A[(size_t)BSZ * 2112];        // feat bf16 (Kpad 2112)
__device__ __nv_bfloat16 g_p1W[(size_t)896 * 4224];        // p1 W hi|lo
__device__ __nv_bfloat16 g_p2A[(size_t)BSZ * 832];         // h1 bf16 (Kpad 832)
__device__ __nv_bfloat16 g_p2W[(size_t)256 * 1664];        // p2 W hi|lo
__device__ float g_H2 [(size_t)BSZ * 200];

__constant__ int c_rowbase[6] = {T_OFF, V_OFF, U_OFF, RT_OFF, RV_OFF, RU_OFF};

// ============================ PTX helpers =======================================
__device__ __forceinline__ uint32_t smem_u32(const void* p) {
    uint32_t a;
    asm("{ .reg .u64 t; cvta.to.shared.u64 t, %1; cvt.u32.u64 %0, t; }" : "=r"(a) : "l"(p));
    return a;
}
__device__ __forceinline__ void cp16(uint32_t dst, const void* src) {
    asm volatile("cp.async.cg.shared.global [%0], [%1], 16;" :: "r"(dst), "l"(src));
}
#define CP_COMMIT() asm volatile("cp.async.commit_group;" ::: "memory")
#define CP_WAIT0()  asm volatile("cp.async.wait_group 0;" ::: "memory")
#define CP_WAIT1()  asm volatile("cp.async.wait_group 1;" ::: "memory")

__device__ __forceinline__ void ldsm_x4(uint32_t& r0, uint32_t& r1, uint32_t& r2, uint32_t& r3,
                                        uint32_t addr) {
    asm volatile("ldmatrix.sync.aligned.m8n8.x4.shared.b16 {%0,%1,%2,%3}, [%4];"
                 : "=r"(r0), "=r"(r1), "=r"(r2), "=r"(r3) : "r"(addr));
}
__device__ __forceinline__ void mma16816(float* d, const uint32_t* a, const uint32_t* b) {
    asm volatile("mma.sync.aligned.m16n8k16.row.col.f32.bf16.bf16.f32 "
                 "{%0,%1,%2,%3}, {%4,%5,%6,%7}, {%8,%9}, {%0,%1,%2,%3};"
                 : "+f"(d[0]), "+f"(d[1]), "+f"(d[2]), "+f"(d[3])
                 : "r"(a[0]), "r"(a[1]), "r"(a[2]), "r"(a[3]), "r"(b[0]), "r"(b[1]));
}
#define SWZ128(b)  ((b) ^ (((b) >> 3) & 0x70))
#define SM_STAGE 49152   // A(16K) + Bh(16K) + Bl(16K)

// 2-term chunk load: A tile once, Bh and Bl tiles of same k-chunk.
__device__ __forceinline__ void load_chunk2(
    const __nv_bfloat16* __restrict__ A, const __nv_bfloat16* __restrict__ B,
    int strideA, int strideB, int koff, int Kpad, int n0, uint32_t sbase, int tid)
{
#pragma unroll
    for (int i = 0; i < 4; i++) {
        int u = tid + i * 256, r = u >> 3, q = u & 7;
        cp16(sbase + SWZ128(r * 128 + q * 16), A + (size_t)r * strideA + koff + q * 8);
    }
#pragma unroll
    for (int i = 0; i < 4; i++) {
        int u = tid + i * 256, r = u >> 3, q = u & 7;
        cp16(sbase + 16384 + SWZ128(r * 128 + q * 16),
             B + (size_t)(n0 + r) * strideB + koff + q * 8);
    }
#pragma unroll
    for (int i = 0; i < 4; i++) {
        int u = tid + i * 256, r = u >> 3, q = u & 7;
        cp16(sbase + 32768 + SWZ128(r * 128 + q * 16),
             B + (size_t)(n0 + r) * strideB + Kpad + koff + q * 8);
    }
}

// compute one 64-K chunk: A regs reused for both B terms
__device__ __forceinline__ void compute_chunk2(uint32_t base, int warp_m, int warp_n,
                                               int lane, float acc[4][4][4])
{
#pragma unroll
    for (int ks = 0; ks < 4; ks++) {
        uint32_t a[4][4];
#pragma unroll
        for (int mt = 0; mt < 4; mt++) {
            int row = warp_m * 64 + mt * 16 + (lane & 15);
            int byo = row * 128 + ks * 32 + ((lane >> 4) & 1) * 16;
            ldsm_x4(a[mt][0], a[mt][1], a[mt][2], a[mt][3], base + SWZ128(byo));
        }
        uint32_t b[2][4];
#pragma unroll
        for (int np = 0; np < 2; np++) {
            int nrow = warp_n * 32 + np * 16 + ((lane >> 4) & 1) * 8 + (lane & 7);
            int byo = nrow * 128 + ks * 32 + ((lane >> 3) & 1) * 16;
            ldsm_x4(b[np][0], b[np][1], b[np][2], b[np][3], base + 16384 + SWZ128(byo));
        }
#pragma unroll
        for (int mt = 0; mt < 4; mt++)
#pragma unroll
            for (int nt = 0; nt < 4; nt++)
                mma16816(acc[mt][nt], a[mt], &b[nt >> 1][(nt & 1) * 2]);
#pragma unroll
        for (int np = 0; np < 2; np++) {
            int nrow = warp_n * 32 + np * 16 + ((lane >> 4) & 1) * 8 + (lane & 7);
            int byo = nrow * 128 + ks * 32 + ((lane >> 3) & 1) * 16;
            ldsm_x4(b[np][0], b[np][1], b[np][2], b[np][3], base + 32768 + SWZ128(byo));
        }
#pragma unroll
        for (int mt = 0; mt < 4; mt++)
#pragma unroll
            for (int nt = 0; nt < 4; nt++)
                mma16816(acc[mt][nt], a[mt], &b[nt >> 1][(nt & 1) * 2]);
    }
}

// ======================= conversion kernels =====================================
__global__ void conv_hi(const float* __restrict__ src, __nv_bfloat16* __restrict__ dst,
                        int nrows)   // [nrows x 768] fp32 -> bf16 hi
{
    int i = blockIdx.x * blockDim.x + threadIdx.x;
    int total = nrows * (FD / 4);
    if (i >= total) return;
    int row = i / (FD / 4), c4 = (i % (FD / 4)) * 4;
    float4 x = *reinterpret_cast<const float4*>(src + (size_t)row * FD + c4);
    __nv_bfloat162 p0, p1;
    p0.x = __float2bfloat16(x.x); p0.y = __float2bfloat16(x.y);
    p1.x = __float2bfloat16(x.z); p1.y = __float2bfloat16(x.w);
    uint2 v;
    v.x = *reinterpret_cast<uint32_t*>(&p0);
    v.y = *reinterpret_cast<uint32_t*>(&p1);
    *reinterpret_cast<uint2*>(dst + (size_t)row * FD + c4) = v;
}

__global__ void conv_w(const float* __restrict__ w, __nv_bfloat16* __restrict__ dst)
{   // [500 x 768] -> [512 x 1536] hi|lo
    int i = blockIdx.x * blockDim.x + threadIdx.x;
    if (i >= 512 * FD) return;
    int row = i / FD, col = i % FD;
    float x = (row < PD) ? w[(size_t)row * FD + col] : 0.f;
    __nv_bfloat16 h = __float2bfloat16(x);
    __nv_bfloat16 l = __float2bfloat16(x - __bfloat162float(h));
    dst[(size_t)row * 1536 + col] = h;
    dst[(size_t)row * 1536 + FD + col] = l;
}

// float [rows_src x Kreal] -> bf16 [rows_dst x 2*Kpad] hi|lo, zero padded
__global__ void conv_split(const float* __restrict__ src, __nv_bfloat16* __restrict__ dst,
                           int rows_src, int Kreal, int Kpad, long long total)
{
    long long i = (long long)blockIdx.x * blockDim.x + threadIdx.x;
    if (i >= total) return;
    int col = (int)(i % Kpad);
    long long row = i / Kpad;
    float x = (row < rows_src && col < Kreal) ? src[row * Kreal + col] : 0.f;
    __nv_bfloat16 h = __float2bfloat16(x);
    __nv_bfloat16 l = __float2bfloat16(x - __bfloat162float(h));
    dst[row * (2 * (long long)Kpad) + col] = h;
    dst[row * (2 * (long long)Kpad) + Kpad + col] = l;
}

// float [rows_src x Kreal] -> bf16 [rows_dst x Kpad] hi only, zero padded
__global__ void conv_hi_pad(const float* __restrict__ src, __nv_bfloat16* __restrict__ dst,
                            int rows_src, int Kreal, int Kpad, long long total)
{
    long long i = (long long)blockIdx.x * blockDim.x + threadIdx.x;
    if (i >= total) return;
    int col = (int)(i % Kpad);
    long long row = i / Kpad;
    float x = (row < rows_src && col < Kreal) ? src[row * Kreal + col] : 0.f;
    dst[row * Kpad + col] = __float2bfloat16(x);
}

// ================= unified projection GEMM (6 segments, fused epilogue) =========
struct ProjArgs {
    const __nv_bfloat16* A;
    const __nv_bfloat16* B[6];
    const float* bias[6];
    float* Mo;
};

__global__ __launch_bounds__(256) void proj_gemm(ProjArgs args)
{
    extern __shared__ char smem[];
    const uint32_t sb = smem_u32(smem);
    const int tid = threadIdx.x, lane = tid & 31, wid = tid >> 5;
    const int warp_m = wid >> 2, warp_n = wid & 3;
    const int n0 = blockIdx.x * 128;
    const int ty = blockIdx.y;

    int seg, tstart;
    if (ty < 96)       { seg = ty >> 5; tstart = seg << 5; }
    else if (ty < 416) { seg = 3; tstart = 96; }
    else if (ty < 736) { seg = 4; tstart = 416; }
    else               { seg = 5; tstart = 736; }
    const int tl = ty - tstart;
    const __nv_bfloat16* A = args.A + (size_t)(c_rowbase[seg] + tl * 128) * FD;
    const __nv_bfloat16* B = args.B[seg];
    const float* bias = args.bias[seg];
    float* Mo = args.Mo;

    float acc[4][4][4];
#pragma unroll
    for (int i = 0; i < 4; i++)
#pragma unroll
        for (int j = 0; j < 4; j++)
#pragma unroll
            for (int k = 0; k < 4; k++) acc[i][j][k] = 0.f;

    const int kc = 12;   // 768/64
    load_chunk2(A, B, FD, 1536, 0, FD, n0, sb, tid);
    CP_COMMIT();
    for (int c = 0; c < kc; c++) {
        if (c + 1 < kc) {
            load_chunk2(A, B, FD, 1536, (c + 1) * 64, FD, n0, sb + ((c + 1) & 1) * SM_STAGE, tid);
            CP_COMMIT();
            CP_WAIT1();
        } else CP_WAIT0();
        __syncthreads();
        compute_chunk2(sb + (c & 1) * SM_STAGE, warp_m, warp_n, lane, acc);
        __syncthreads();
    }

    if (seg < 3) {
        // direct: one row per sample -> g_M[(b*6+seg)*500 + n]
#pragma unroll
        for (int mt = 0; mt < 4; mt++) {
            int r0 = warp_m * 64 + mt * 16 + (lane >> 2);
#pragma unroll
            for (int nt = 0; nt < 4; nt++) {
                int c0 = warp_n * 32 + nt * 8 + (lane & 3) * 2;
#pragma unroll
                for (int q = 0; q < 4; q++) {
                    int r = r0 + ((q >> 1) ? 8 : 0);
                    int cc = n0 + c0 + (q & 1);
                    if (cc < PD) {
                        float v = tanhf(acc[mt][nt][q] + bias[cc]);
                        Mo[((size_t)(tl * 128 + r) * 6 + seg) * PD + cc] = v;
                    }
                }
            }
        }
    } else {
        // reduce: stage tanh values in smem, sum per sample, atomicAdd
        float* sred = (float*)smem;
#pragma unroll
        for (int mt = 0; mt < 4; mt++) {
            int r0 = warp_m * 64 + mt * 16 + (lane >> 2);
#pragma unroll
            for (int nt = 0; nt < 4; nt++) {
                int c0 = warp_n * 32 + nt * 8 + (lane & 3) * 2;
#pragma unroll
                for (int q = 0; q < 4; q++) {
                    int r = r0 + ((q >> 1) ? 8 : 0);
                    int cl = c0 + (q & 1);
                    int cc = n0 + cl;
                    float v = tanhf(acc[mt][nt][q] + bias[cc < PD ? cc : PD - 1]);
                    sred[r * 132 + cl] = v;
                }
            }
        }
        __syncthreads();
        const int r0g = tl * 128;
        const int sfirst = r0g / 10, slast = (r0g + 127) / 10;
        const int ns = slast - sfirst + 1;
        for (int idx = tid; idx < ns * 128; idx += 256) {
            int si = idx >> 7, cl = idx & 127;
            int cc = n0 + cl;
            if (cc >= PD) continue;
            int s = sfirst + si;
            int lo = s * 10 - r0g;     if (lo < 0) lo = 0;
            int hi = s * 10 + 9 - r0g; if (hi > 127) hi = 127;
            float sum = 0.f;
            for (int r = lo; r <= hi; r++) sum += sred[r * 132 + cl];
            atomicAdd(&Mo[((size_t)s * 6 + seg) * PD + cc], sum);
        }
        if (tl == 0 && seg != 5) {
            int rb = (seg == 3) ? M_BASE : M_BASE + RNUM;
            for (int idx = tid; idx < 10 * 128; idx += 256) {
                int r = idx >> 7, cl = idx & 127;
                int cc = n0 + cl;
                if (cc < PD) Mo[((size_t)(rb + r)) * PD + cc] = sred[r * 132 + cl];
            }
        }
    }
}

// ===================== generic 2-term HMMA GEMM =================================
__global__ __launch_bounds__(256) void mma_gemm2(
    const __nv_bfloat16* __restrict__ A, const __nv_bfloat16* __restrict__ B,
    const float* __restrict__ bias, void* __restrict__ Cout,
    int M, int Nreal, int ostride, int Kpad, int act, int outbf16)
{
    extern __shared__ char smem[];
    const uint32_t sb = smem_u32(smem);
    const int tid = threadIdx.x, lane = tid & 31, wid = tid >> 5;
    const int warp_m = wid >> 2, warp_n = wid & 3;
    const int m0 = blockIdx.y * 128, n0 = blockIdx.x * 128;
    const __nv_bfloat16* At = A + (size_t)m0 * Kpad;
    const int kc = Kpad >> 6;

    float acc[4][4][4];
#pragma unroll
    for (int i = 0; i < 4; i++)
#pragma unroll
        for (int j = 0; j < 4; j++)
#pragma unroll
            for (int k = 0; k < 4; k++) acc[i][j][k] = 0.f;

    load_chunk2(At, B, Kpad, 2 * Kpad, 0, Kpad, n0, sb, tid);
    CP_COMMIT();
    for (int c = 0; c < kc; c++) {
        if (c + 1 < kc) {
            load_chunk2(At, B, Kpad, 2 * Kpad, (c + 1) * 64, Kpad, n0,
                        sb + ((c + 1) & 1) * SM_STAGE, tid);
            CP_COMMIT();
            CP_WAIT1();
        } else CP_WAIT0();
        __syncthreads();
        compute_chunk2(sb + (c & 1) * SM_STAGE, warp_m, warp_n, lane, acc);
        __syncthreads();
    }

#pragma unroll
    for (int mt = 0; mt < 4; mt++) {
        int r0 = m0 + warp_m * 64 + mt * 16 + (lane >> 2);
#pragma unroll
        for (int nt = 0; nt < 4; nt++) {
            int c0 = n0 + warp_n * 32 + nt * 8 + (lane & 3) * 2;
#pragma unroll
            for (int q = 0; q < 4; q++) {
                int r = r0 + ((q >> 1) ? 8 : 0);
                int cc = c0 + (q & 1);
                if (r < M && cc < Nreal) {
                    float v = acc[mt][nt][q];
                    if (bias) v += bias[cc];
                    if (act == 1)      v = tanhf(v);
                    else if (act == 2) v = fmaxf(v, 0.f);
                    if (outbf16)
                        ((__nv_bfloat16*)Cout)[(size_t)r * ostride + cc] = __float2bfloat16(v);
                    else
                        ((float*)Cout)[(size_t)r * ostride + cc] = v;
                }
            }
        }
    }
}

// ------------ K4: hypergraph closed-form epilogue -> bf16 feat ------------------
__global__ void epilogue(const float* __restrict__ Z, const float* __restrict__ hg_b,
                         const float* __restrict__ sim, const float* __restrict__ rlabel,
                         const float* __restrict__ lbl_w, const float* __restrict__ lbl_b,
                         __nv_bfloat16* __restrict__ F)
{
    int b = blockIdx.x;
    __shared__ float sw[RNUM];
    __shared__ float slbl;
    if (threadIdx.x == 0) {
        float mx = -1e30f;
        for (int i = 0; i < RNUM; i++) mx = fmaxf(mx, sim[b * RNUM + i]);
        float s = 0.f;
        for (int i = 0; i < RNUM; i++) { sw[i] = expf(sim[b * RNUM + i] - mx); s += sw[i]; }
        float inv = 1.f / s;
        float la = 0.f;
        for (int i = 0; i < RNUM; i++) { sw[i] *= inv; la += sw[i] * rlabel[b * RNUM + i]; }
        slbl = la;
    }
    __syncthreads();
    float lblagg = slbl;

    for (int d = threadIdx.x; d < ZD; d += blockDim.x) {
        float hb = hg_b[d];
        size_t ro = (size_t)b * 6 * ZD;
        float xt_t = Z[ro + 0 * ZD + d] + hb;
        float xt_v = Z[ro + 1 * ZD + d] + hb;
        float xt_u = Z[ro + 2 * ZD + d] + hb;
        float s1   = Z[ro + 3 * ZD + d] + 10.f * hb;
        float s2   = Z[ro + 4 * ZD + d] + 10.f * hb;
        float s3   = Z[ro + 5 * ZD + d] + 10.f * hb;

        float yg0 = (xt_t + xt_v + xt_u) * (1.f / 3.f);
        float yg1 = (s1 + xt_t) * (1.f / 11.f);
        float yg2 = (s2 + xt_v) * (1.f / 11.f);
        float yg3 = (s3 + xt_u) * (1.f / 11.f);

        float xo0 = fmaxf(0.5f * (yg0 + yg1), 0.f);
        float xo1 = fmaxf(0.5f * (yg0 + yg2), 0.f);
        float xo2 = fmaxf(0.5f * (yg0 + yg3), 0.f);

        float rt_agg, rv_agg;
        if (b == 0) {
            rt_agg = 0.f; rv_agg = 0.f;
#pragma unroll
            for (int i = 0; i < RNUM; i++) {
                float xt_rt = Z[(size_t)(M_BASE + i) * ZD + d] + hb;
                float xt_rv = Z[(size_t)(M_BASE + RNUM + i) * ZD + d] + hb;
                float yp = 0.5f * (xt_rt + xt_rv);
                rt_agg += sw[i] * fmaxf(0.5f * (yg1 + yp), 0.f);
                rv_agg += sw[i] * fmaxf(0.5f * (yg2 + yp), 0.f);
            }
        } else {
            rt_agg = fmaxf(yg1, 0.f);
            rv_agg = fmaxf(yg2, 0.f);
        }
        float ru_agg = fmaxf(yg3, 0.f);
        float le = fmaxf(lbl_w[d] * lblagg + lbl_b[d], 0.f);

        __nv_bfloat16* Fr = F + (size_t)b * 2112;
        Fr[          d] = __float2bfloat16(xo0);
        Fr[ 300 +    d] = __float2bfloat16(xo1);
        Fr[ 600 +    d] = __float2bfloat16(xo2);
        Fr[ 900 +    d] = __float2bfloat16(rv_agg);
        Fr[1200 +    d] = __float2bfloat16(rt_agg);
        Fr[1500 +    d] = __float2bfloat16(ru_agg);
        Fr[1800 +    d] = __float2bfloat16(le);
    }
}

// ------------ final 200->1 dot + sigmoid ---------------------------------------
__global__ void final_head(const float* __restrict__ H2, const float* __restrict__ w,
                           const float* __restrict__ b, float* __restrict__ out)
{
    int row  = blockIdx.x * (blockDim.x >> 5) + (threadIdx.x >> 5);
    int lane = threadIdx.x & 31;
    if (row >= BSZ) return;
    float s = 0.f;
    for (int j = lane; j < 200; j += 32) s += H2[(size_t)row * 200 + j] * w[j];
#pragma unroll
    for (int off = 16; off > 0; off >>= 1)
        s += __shfl_xor_sync(0xFFFFFFFFu, s, off);
    if (lane == 0) out[row] = 1.f / (1.f + expf(-(s + b[0])));
}

// -------------------------------- launch ---------------------------------------
extern "C" void kernel_launch(void* const* d_in, const int* in_sizes, int n_in,
                              void* d_out, int out_size)
{
    const float* visual  = (const float*)d_in[0];
    const float* textual = (const float*)d_in[1];
    const float* sim     = (const float*)d_in[2];
    const float* rvis    = (const float*)d_in[3];
    const float* rtxt    = (const float*)d_in[4];
    const float* rlabel  = (const float*)d_in[5];
    const float* user    = (const float*)d_in[6];
    const float* ruser   = (const float*)d_in[7];
    const float* vis_w = (const float*)d_in[9],  *vis_b = (const float*)d_in[10];
    const float* txt_w = (const float*)d_in[11], *txt_b = (const float*)d_in[12];
    const float* usr_w = (const float*)d_in[13], *usr_b = (const float*)d_in[14];
    const float* rvis_w = (const float*)d_in[15], *rvis_b = (const float*)d_in[16];
    const float* rtxt_w = (const float*)d_in[17], *rtxt_b = (const float*)d_in[18];
    const float* rusr_w = (const float*)d_in[19], *rusr_b = (const float*)d_in[20];
    const float* hg_w = (const float*)d_in[21], *hg_b = (const float*)d_in[22];
    const float* lbl_w = (const float*)d_in[23], *lbl_b = (const float*)d_in[24];
    const float* p1_w = (const float*)d_in[25], *p1_b = (const float*)d_in[26];
    const float* p2_w = (const float*)d_in[27], *p2_b = (const float*)d_in[28];
    const float* p3_w = (const float*)d_in[29], *p3_b = (const float*)d_in[30];

    float *mbuf, *z, *h2;
    __nv_bfloat16 *abf, *bbf, *hgA, *hgW, *p1A, *p1W, *p2A, *p2W;
    cudaGetSymbolAddress((void**)&abf,  g_Abf);
    cudaGetSymbolAddress((void**)&bbf,  g_Bbf);
    cudaGetSymbolAddress((void**)&mbuf, g_M);
    cudaGetSymbolAddress((void**)&hgA,  g_hgA);
    cudaGetSymbolAddress((void**)&hgW,  g_hgW);
    cudaGetSymbolAddress((void**)&z,    g_Z);
    cudaGetSymbolAddress((void**)&p1A,  g_p1A);
    cudaGetSymbolAddress((void**)&p1W,  g_p1W);
    cudaGetSymbolAddress((void**)&p2A,  g_p2A);
    cudaGetSymbolAddress((void**)&p2W,  g_p2W);
    cudaGetSymbolAddress((void**)&h2,   g_H2);

    cudaFuncSetAttribute(proj_gemm, cudaFuncAttributeMaxDynamicSharedMemorySize, 2 * SM_STAGE);
    cudaFuncSetAttribute(mma_gemm2, cudaFuncAttributeMaxDynamicSharedMemorySize, 2 * SM_STAGE);

    const int CT = 256;
    // zero accumulation target (atomics add into it)
    cudaMemsetAsync(mbuf, 0, (size_t)M_ROWS * PD * sizeof(float));

    // ---- convert inputs to bf16 (hi only) ----
    auto cvA = [&](const float* src, int doff, int rows) {
        int tot = rows * (FD / 4);
        conv_hi<<<(tot + CT - 1) / CT, CT>>>(src, abf + (size_t)doff * FD, rows);
    };
    cvA(textual, T_OFF,  BSZ);
    cvA(visual,  V_OFF,  BSZ);
    cvA(user,    U_OFF,  BSZ);
    cvA(rtxt,    RT_OFF, BSZ * RNUM);
    cvA(rvis,    RV_OFF, BSZ * RNUM);
    cvA(ruser,   RU_OFF, BSZ * UNUM);

    // ---- convert weights (proj hi|lo, hg/p1/p2 hi|lo) ----
    const float* ws[6] = {txt_w, vis_w, usr_w, rtxt_w, rvis_w, rusr_w};
    for (int i = 0; i < 6; i++)
        conv_w<<<(512 * FD + CT - 1) / CT, CT>>>(ws[i], bbf + (size_t)i * 512 * 1536);
    {
        long long tot = (long long)384 * 512;
        conv_split<<<(unsigned)((tot + CT - 1) / CT), CT>>>(hg_w, hgW, ZD, PD, 512, tot);
        tot = (long long)896 * 2112;
        conv_split<<<(unsigned)((tot + CT - 1) / CT), CT>>>(p1_w, p1W, 800, 2100, 2112, tot);
        tot = (long long)256 * 832;
        conv_split<<<(unsigned)((tot + CT - 1) / CT), CT>>>(p2_w, p2W, 200, 800, 832, tot);
    }

    // ---- unified projection GEMM (6 segments, fused tanh + group-sum) ----
    {
        ProjArgs pa;
        pa.A = abf;
        for (int i = 0; i < 6; i++) pa.B[i] = bbf + (size_t)i * 512 * 1536;
        pa.bias[0] = txt_b; pa.bias[1] = vis_b; pa.bias[2] = usr_b;
        pa.bias[3] = rtxt_b; pa.bias[4] = rvis_b; pa.bias[5] = rusr_b;
        pa.Mo = mbuf;
        dim3 g(4, 1056);
        proj_gemm<<<g, 256, 2 * SM_STAGE>>>(pa);
    }

    // ---- hg: conv A then GEMM (bias handled in epilogue) ----
    {
        long long tot = (long long)M_PAD_HG * 512;
        conv_hi_pad<<<(unsigned)((tot + CT - 1) / CT), CT>>>(mbuf, hgA, M_ROWS, PD, 512, tot);
        dim3 g(3, M_PAD_HG / 128);
        mma_gemm2<<<g, 256, 2 * SM_STAGE>>>(hgA, hgW, nullptr, z, M_ROWS, ZD, ZD, 512, 0, 0);
    }

    // ---- closed-form hypergraph conv + feat assembly (bf16 out) ----
    epilogue<<<BSZ, 128>>>(z, hg_b, sim, rlabel, lbl_w, lbl_b, p1A);

    // ---- p1: relu, bf16 out into p2A (stride 832) ----
    {
        dim3 g(7, BSZ / 128);
        mma_gemm2<<<g, 256, 2 * SM_STAGE>>>(p1A, p1W, p1_b, p2A, BSZ, 800, 832, 2112, 2, 1);
    }
    // ---- p2: relu, fp32 out ----
    {
        dim3 g(2, BSZ / 128);
        mma_gemm2<<<g, 256, 2 * SM_STAGE>>>(p2A, p2W, p2_b, h2, BSZ, 200, 200, 832, 2, 0);
    }
    // ---- sigmoid head ----
    final_head<<<(BSZ * 32 + 255) / 256, 256>>>(h2, p3_w, p3_b, (float*)d_out);
}

// round 11
// speedup vs baseline: 7.2584x; 1.6224x over previous
#include <cuda_runtime.h>
#include <cuda_bf16.h>
#include <cstdint>
#include <math.h>

#define BSZ   4096
#define FD    768
#define PD    500
#define ZD    300
#define RNUM  10
#define UNUM  10

// A segment row offsets (order: t, v, u, rt, rv, ru)
#define T_OFF   0
#define V_OFF   4096
#define U_OFF   8192
#define RT_OFF  12288
#define RV_OFF  53248
#define RU_OFF  94208
#define XP_ROWS 135168
#define M_BASE  24576          // 4096*6 compact rows
#define M_ROWS  24596          // + 20 sample-0 pair rows
#define M_PAD_HG 24704         // 193*128

// -------------------- static scratch (no allocations allowed) -------------------
__device__ __nv_bfloat16 g_Abf[(size_t)XP_ROWS * FD];      // proj inputs bf16
__device__ __nv_bfloat16 g_Bbf[6 * 512 * FD];              // proj weights bf16
__device__ float g_M [(size_t)M_ROWS  * PD];               // group-summed tanh outputs
__device__ __nv_bfloat16 g_hgA[(size_t)M_PAD_HG * 512];    // hg A bf16 (Kpad 512)
__device__ __nv_bfloat16 g_hgW[(size_t)384 * 512];
__device__ float g_Z  [(size_t)M_ROWS  * ZD];
__device__ __nv_bfloat16 g_p1A[(size_t)BSZ * 2112];        // feat bf16 (Kpad 2112)
__device__ __nv_bfloat16 g_p1W[(size_t)896 * 2112];
__device__ __nv_bfloat16 g_p2A[(size_t)BSZ * 832];         // h1 bf16 (Kpad 832)
__device__ __nv_bfloat16 g_p2W[(size_t)256 * 832];
__device__ float g_H2 [(size_t)BSZ * 200];

__constant__ int c_rowbase[6] = {T_OFF, V_OFF, U_OFF, RT_OFF, RV_OFF, RU_OFF};

// ============================ PTX helpers =======================================
__device__ __forceinline__ uint32_t smem_u32(const void* p) {
    uint32_t a;
    asm("{ .reg .u64 t; cvta.to.shared.u64 t, %1; cvt.u32.u64 %0, t; }" : "=r"(a) : "l"(p));
    return a;
}
__device__ __forceinline__ void cp16(uint32_t dst, const void* src) {
    asm volatile("cp.async.cg.shared.global [%0], [%1], 16;" :: "r"(dst), "l"(src));
}
#define CP_COMMIT() asm volatile("cp.async.commit_group;" ::: "memory")
#define CP_WAIT0()  asm volatile("cp.async.wait_group 0;" ::: "memory")
#define CP_WAIT1()  asm volatile("cp.async.wait_group 1;" ::: "memory")

__device__ __forceinline__ void ldsm_x4(uint32_t& r0, uint32_t& r1, uint32_t& r2, uint32_t& r3,
                                        uint32_t addr) {
    asm volatile("ldmatrix.sync.aligned.m8n8.x4.shared.b16 {%0,%1,%2,%3}, [%4];"
                 : "=r"(r0), "=r"(r1), "=r"(r2), "=r"(r3) : "r"(addr));
}
__device__ __forceinline__ void mma16816(float* d, const uint32_t* a, const uint32_t* b) {
    asm volatile("mma.sync.aligned.m16n8k16.row.col.f32.bf16.bf16.f32 "
                 "{%0,%1,%2,%3}, {%4,%5,%6,%7}, {%8,%9}, {%0,%1,%2,%3};"
                 : "+f"(d[0]), "+f"(d[1]), "+f"(d[2]), "+f"(d[3])
                 : "r"(a[0]), "r"(a[1]), "r"(a[2]), "r"(a[3]), "r"(b[0]), "r"(b[1]));
}
#define SWZ128(b)  ((b) ^ (((b) >> 3) & 0x70))
#define SM_STAGE 32768   // A(16K) + B(16K)
#define SMEM_REQ 69632   // 2 stages + room for 128x132 fp32 reduction staging

// chunk load: 128x64 A tile + 128x64 B tile (bf16, SW128)
__device__ __forceinline__ void load_chunk1(
    const __nv_bfloat16* __restrict__ A, const __nv_bfloat16* __restrict__ B,
    int strideA, int strideB, int koff, int n0, uint32_t sbase, int tid)
{
    const int r = tid >> 3, q = tid & 7;
    const uint32_t sa = sbase + SWZ128(r * 128 + q * 16);
    const uint32_t sbB = sbase + 16384 + SWZ128(r * 128 + q * 16);
#pragma unroll
    for (int i = 0; i < 4; i++)
        cp16(sa + i * 4096, A + (size_t)(r + i * 32) * strideA + koff + q * 8);
#pragma unroll
    for (int i = 0; i < 4; i++)
        cp16(sbB + i * 4096, B + (size_t)(n0 + r + i * 32) * strideB + koff + q * 8);
}

// compute one 64-K chunk (pure bf16)
__device__ __forceinline__ void compute_chunk1(uint32_t base, int warp_m, int warp_n,
                                               int lane, float acc[4][4][4])
{
#pragma unroll
    for (int ks = 0; ks < 4; ks++) {
        uint32_t a[4][4], b[2][4];
#pragma unroll
        for (int mt = 0; mt < 4; mt++) {
            int row = warp_m * 64 + mt * 16 + (lane & 15);
            int byo = row * 128 + ks * 32 + ((lane >> 4) & 1) * 16;
            ldsm_x4(a[mt][0], a[mt][1], a[mt][2], a[mt][3], base + SWZ128(byo));
        }
#pragma unroll
        for (int np = 0; np < 2; np++) {
            int nrow = warp_n * 32 + np * 16 + ((lane >> 4) & 1) * 8 + (lane & 7);
            int byo = nrow * 128 + ks * 32 + ((lane >> 3) & 1) * 16;
            ldsm_x4(b[np][0], b[np][1], b[np][2], b[np][3], base + 16384 + SWZ128(byo));
        }
#pragma unroll
        for (int mt = 0; mt < 4; mt++)
#pragma unroll
            for (int nt = 0; nt < 4; nt++)
                mma16816(acc[mt][nt], a[mt], &b[nt >> 1][(nt & 1) * 2]);
    }
}

// ======================= conversion kernels =====================================
__global__ void conv_hi(const float* __restrict__ src, __nv_bfloat16* __restrict__ dst,
                        int nrows)   // [nrows x 768] fp32 -> bf16
{
    int i = blockIdx.x * blockDim.x + threadIdx.x;
    int total = nrows * (FD / 4);
    if (i >= total) return;
    int row = i / (FD / 4), c4 = (i % (FD / 4)) * 4;
    float4 x = *reinterpret_cast<const float4*>(src + (size_t)row * FD + c4);
    __nv_bfloat162 p0, p1;
    p0.x = __float2bfloat16(x.x); p0.y = __float2bfloat16(x.y);
    p1.x = __float2bfloat16(x.z); p1.y = __float2bfloat16(x.w);
    uint2 v;
    v.x = *reinterpret_cast<uint32_t*>(&p0);
    v.y = *reinterpret_cast<uint32_t*>(&p1);
    *reinterpret_cast<uint2*>(dst + (size_t)row * FD + c4) = v;
}

// float [rows_src x Kreal] -> bf16 [rows_dst x Kpad], zero padded
__global__ void conv_hi_pad(const float* __restrict__ src, __nv_bfloat16* __restrict__ dst,
                            int rows_src, int Kreal, int Kpad, long long total)
{
    long long i = (long long)blockIdx.x * blockDim.x + threadIdx.x;
    if (i >= total) return;
    int col = (int)(i % Kpad);
    long long row = i / Kpad;
    float x = (row < rows_src && col < Kreal) ? src[row * Kreal + col] : 0.f;
    dst[row * Kpad + col] = __float2bfloat16(x);
}

// ================= unified projection GEMM (6 segments, fused epilogue) =========
struct ProjArgs {
    const __nv_bfloat16* A;
    const __nv_bfloat16* B[6];
    const float* bias[6];
    float* Mo;
};

__global__ __launch_bounds__(256) void proj_gemm(ProjArgs args)
{
    extern __shared__ char smem[];
    const uint32_t sb = smem_u32(smem);
    const int tid = threadIdx.x, lane = tid & 31, wid = tid >> 5;
    const int warp_m = wid >> 2, warp_n = wid & 3;
    const int n0 = blockIdx.x * 128;
    const int ty = blockIdx.y;

    int seg, tstart;
    if (ty < 96)       { seg = ty >> 5; tstart = seg << 5; }
    else if (ty < 416) { seg = 3; tstart = 96; }
    else if (ty < 736) { seg = 4; tstart = 416; }
    else               { seg = 5; tstart = 736; }
    const int tl = ty - tstart;
    const __nv_bfloat16* A = args.A + (size_t)(c_rowbase[seg] + tl * 128) * FD;
    const __nv_bfloat16* B = args.B[seg];
    const float* bias = args.bias[seg];
    float* Mo = args.Mo;

    float acc[4][4][4];
#pragma unroll
    for (int i = 0; i < 4; i++)
#pragma unroll
        for (int j = 0; j < 4; j++)
#pragma unroll
            for (int k = 0; k < 4; k++) acc[i][j][k] = 0.f;

    const int kc = 12;   // 768/64
    load_chunk1(A, B, FD, FD, 0, n0, sb, tid);
    CP_COMMIT();
    for (int c = 0; c < kc; c++) {
        if (c + 1 < kc) {
            load_chunk1(A, B, FD, FD, (c + 1) * 64, n0, sb + ((c + 1) & 1) * SM_STAGE, tid);
            CP_COMMIT();
            CP_WAIT1();
        } else CP_WAIT0();
        __syncthreads();
        compute_chunk1(sb + (c & 1) * SM_STAGE, warp_m, warp_n, lane, acc);
        __syncthreads();
    }

    if (seg < 3) {
        // direct: one row per sample -> g_M[(b*6+seg)*500 + n]
#pragma unroll
        for (int mt = 0; mt < 4; mt++) {
            int r0 = warp_m * 64 + mt * 16 + (lane >> 2);
#pragma unroll
            for (int nt = 0; nt < 4; nt++) {
                int c0 = warp_n * 32 + nt * 8 + (lane & 3) * 2;
#pragma unroll
                for (int q = 0; q < 4; q++) {
                    int r = r0 + ((q >> 1) ? 8 : 0);
                    int cc = n0 + c0 + (q & 1);
                    if (cc < PD) {
                        float v = tanhf(acc[mt][nt][q] + bias[cc]);
                        Mo[((size_t)(tl * 128 + r) * 6 + seg) * PD + cc] = v;
                    }
                }
            }
        }
    } else {
        // reduce: stage tanh values in smem, sum per sample, atomicAdd
        float* sred = (float*)smem;
#pragma unroll
        for (int mt = 0; mt < 4; mt++) {
            int r0 = warp_m * 64 + mt * 16 + (lane >> 2);
#pragma unroll
            for (int nt = 0; nt < 4; nt++) {
                int c0 = warp_n * 32 + nt * 8 + (lane & 3) * 2;
#pragma unroll
                for (int q = 0; q < 4; q++) {
                    int r = r0 + ((q >> 1) ? 8 : 0);
                    int cl = c0 + (q & 1);
                    int cc = n0 + cl;
                    float v = tanhf(acc[mt][nt][q] + bias[cc < PD ? cc : PD - 1]);
                    sred[r * 132 + cl] = v;
                }
            }
        }
        __syncthreads();
        const int r0g = tl * 128;
        const int sfirst = r0g / 10, slast = (r0g + 127) / 10;
        const int ns = slast - sfirst + 1;
        for (int idx = tid; idx < ns * 128; idx += 256) {
            int si = idx >> 7, cl = idx & 127;
            int cc = n0 + cl;
            if (cc >= PD) continue;
            int s = sfirst + si;
            int lo = s * 10 - r0g;     if (lo < 0) lo = 0;
            int hi = s * 10 + 9 - r0g; if (hi > 127) hi = 127;
            float sum = 0.f;
            for (int r = lo; r <= hi; r++) sum += sred[r * 132 + cl];
            atomicAdd(&Mo[((size_t)s * 6 + seg) * PD + cc], sum);
        }
        if (tl == 0 && seg != 5) {
            int rb = (seg == 3) ? M_BASE : M_BASE + RNUM;
            for (int idx = tid; idx < 10 * 128; idx += 256) {
                int r = idx >> 7, cl = idx & 127;
                int cc = n0 + cl;
                if (cc < PD) Mo[((size_t)(rb + r)) * PD + cc] = sred[r * 132 + cl];
            }
        }
    }
}

// ===================== generic bf16 HMMA GEMM ===================================
__global__ __launch_bounds__(256) void mma_gemm1(
    const __nv_bfloat16* __restrict__ A, const __nv_bfloat16* __restrict__ B,
    const float* __restrict__ bias, void* __restrict__ Cout,
    int M, int Nreal, int ostride, int Kpad, int act, int outbf16)
{
    extern __shared__ char smem[];
    const uint32_t sb = smem_u32(smem);
    const int tid = threadIdx.x, lane = tid & 31, wid = tid >> 5;
    const int warp_m = wid >> 2, warp_n = wid & 3;
    const int m0 = blockIdx.y * 128, n0 = blockIdx.x * 128;
    const __nv_bfloat16* At = A + (size_t)m0 * Kpad;
    const int kc = Kpad >> 6;

    float acc[4][4][4];
#pragma unroll
    for (int i = 0; i < 4; i++)
#pragma unroll
        for (int j = 0; j < 4; j++)
#pragma unroll
            for (int k = 0; k < 4; k++) acc[i][j][k] = 0.f;

    load_chunk1(At, B, Kpad, Kpad, 0, n0, sb, tid);
    CP_COMMIT();
    for (int c = 0; c < kc; c++) {
        if (c + 1 < kc) {
            load_chunk1(At, B, Kpad, Kpad, (c + 1) * 64, n0,
                        sb + ((c + 1) & 1) * SM_STAGE, tid);
            CP_COMMIT();
            CP_WAIT1();
        } else CP_WAIT0();
        __syncthreads();
        compute_chunk1(sb + (c & 1) * SM_STAGE, warp_m, warp_n, lane, acc);
        __syncthreads();
    }

#pragma unroll
    for (int mt = 0; mt < 4; mt++) {
        int r0 = m0 + warp_m * 64 + mt * 16 + (lane >> 2);
#pragma unroll
        for (int nt = 0; nt < 4; nt++) {
            int c0 = n0 + warp_n * 32 + nt * 8 + (lane & 3) * 2;
#pragma unroll
            for (int q = 0; q < 4; q++) {
                int r = r0 + ((q >> 1) ? 8 : 0);
                int cc = c0 + (q & 1);
                if (r < M && cc < Nreal) {
                    float v = acc[mt][nt][q];
                    if (bias) v += bias[cc];
                    if (act == 1)      v = tanhf(v);
                    else if (act == 2) v = fmaxf(v, 0.f);
                    if (outbf16)
                        ((__nv_bfloat16*)Cout)[(size_t)r * ostride + cc] = __float2bfloat16(v);
                    else
                        ((float*)Cout)[(size_t)r * ostride + cc] = v;
                }
            }
        }
    }
}

// ------------ K4: hypergraph closed-form epilogue -> bf16 feat ------------------
__global__ void epilogue(const float* __restrict__ Z, const float* __restrict__ hg_b,
                         const float* __restrict__ sim, const float* __restrict__ rlabel,
                         const float* __restrict__ lbl_w, const float* __restrict__ lbl_b,
                         __nv_bfloat16* __restrict__ F)
{
    int b = blockIdx.x;
    __shared__ float sw[RNUM];
    __shared__ float slbl;
    if (threadIdx.x == 0) {
        float mx = -1e30f;
        for (int i = 0; i < RNUM; i++) mx = fmaxf(mx, sim[b * RNUM + i]);
        float s = 0.f;
        for (int i = 0; i < RNUM; i++) { sw[i] = expf(sim[b * RNUM + i] - mx); s += sw[i]; }
        float inv = 1.f / s;
        float la = 0.f;
        for (int i = 0; i < RNUM; i++) { sw[i] *= inv; la += sw[i] * rlabel[b * RNUM + i]; }
        slbl = la;
    }
    __syncthreads();
    float lblagg = slbl;

    for (int d = threadIdx.x; d < ZD; d += blockDim.x) {
        float hb = hg_b[d];
        size_t ro = (size_t)b * 6 * ZD;
        float xt_t = Z[ro + 0 * ZD + d] + hb;
        float xt_v = Z[ro + 1 * ZD + d] + hb;
        float xt_u = Z[ro + 2 * ZD + d] + hb;
        float s1   = Z[ro + 3 * ZD + d] + 10.f * hb;
        float s2   = Z[ro + 4 * ZD + d] + 10.f * hb;
        float s3   = Z[ro + 5 * ZD + d] + 10.f * hb;

        float yg0 = (xt_t + xt_v + xt_u) * (1.f / 3.f);
        float yg1 = (s1 + xt_t) * (1.f / 11.f);
        float yg2 = (s2 + xt_v) * (1.f / 11.f);
        float yg3 = (s3 + xt_u) * (1.f / 11.f);

        float xo0 = fmaxf(0.5f * (yg0 + yg1), 0.f);
        float xo1 = fmaxf(0.5f * (yg0 + yg2), 0.f);
        float xo2 = fmaxf(0.5f * (yg0 + yg3), 0.f);

        float rt_agg, rv_agg;
        if (b == 0) {
            rt_agg = 0.f; rv_agg = 0.f;
#pragma unroll
            for (int i = 0; i < RNUM; i++) {
                float xt_rt = Z[(size_t)(M_BASE + i) * ZD + d] + hb;
                float xt_rv = Z[(size_t)(M_BASE + RNUM + i) * ZD + d] + hb;
                float yp = 0.5f * (xt_rt + xt_rv);
                rt_agg += sw[i] * fmaxf(0.5f * (yg1 + yp), 0.f);
                rv_agg += sw[i] * fmaxf(0.5f * (yg2 + yp), 0.f);
            }
        } else {
            rt_agg = fmaxf(yg1, 0.f);
            rv_agg = fmaxf(yg2, 0.f);
        }
        float ru_agg = fmaxf(yg3, 0.f);
        float le = fmaxf(lbl_w[d] * lblagg + lbl_b[d], 0.f);

        __nv_bfloat16* Fr = F + (size_t)b * 2112;
        Fr[          d] = __float2bfloat16(xo0);
        Fr[ 300 +    d] = __float2bfloat16(xo1);
        Fr[ 600 +    d] = __float2bfloat16(xo2);
        Fr[ 900 +    d] = __float2bfloat16(rv_agg);
        Fr[1200 +    d] = __float2bfloat16(rt_agg);
        Fr[1500 +    d] = __float2bfloat16(ru_agg);
        Fr[1800 +    d] = __float2bfloat16(le);
    }
}

// ------------ final 200->1 dot + sigmoid ---------------------------------------
__global__ void final_head(const float* __restrict__ H2, const float* __restrict__ w,
                           const float* __restrict__ b, float* __restrict__ out)
{
    int row  = blockIdx.x * (blockDim.x >> 5) + (threadIdx.x >> 5);
    int lane = threadIdx.x & 31;
    if (row >= BSZ) return;
    float s = 0.f;
    for (int j = lane; j < 200; j += 32) s += H2[(size_t)row * 200 + j] * w[j];
#pragma unroll
    for (int off = 16; off > 0; off >>= 1)
        s += __shfl_xor_sync(0xFFFFFFFFu, s, off);
    if (lane == 0) out[row] = 1.f / (1.f + expf(-(s + b[0])));
}

// -------------------------------- launch ---------------------------------------
extern "C" void kernel_launch(void* const* d_in, const int* in_sizes, int n_in,
                              void* d_out, int out_size)
{
    const float* visual  = (const float*)d_in[0];
    const float* textual = (const float*)d_in[1];
    const float* sim     = (const float*)d_in[2];
    const float* rvis    = (const float*)d_in[3];
    const float* rtxt    = (const float*)d_in[4];
    const float* rlabel  = (const float*)d_in[5];
    const float* user    = (const float*)d_in[6];
    const float* ruser   = (const float*)d_in[7];
    const float* vis_w = (const float*)d_in[9],  *vis_b = (const float*)d_in[10];
    const float* txt_w = (const float*)d_in[11], *txt_b = (const float*)d_in[12];
    const float* usr_w = (const float*)d_in[13], *usr_b = (const float*)d_in[14];
    const float* rvis_w = (const float*)d_in[15], *rvis_b = (const float*)d_in[16];
    const float* rtxt_w = (const float*)d_in[17], *rtxt_b = (const float*)d_in[18];
    const float* rusr_w = (const float*)d_in[19], *rusr_b = (const float*)d_in[20];
    const float* hg_w = (const float*)d_in[21], *hg_b = (const float*)d_in[22];
    const float* lbl_w = (const float*)d_in[23], *lbl_b = (const float*)d_in[24];
    const float* p1_w = (const float*)d_in[25], *p1_b = (const float*)d_in[26];
    const float* p2_w = (const float*)d_in[27], *p2_b = (const float*)d_in[28];
    const float* p3_w = (const float*)d_in[29], *p3_b = (const float*)d_in[30];

    float *mbuf, *z, *h2;
    __nv_bfloat16 *abf, *bbf, *hgA, *hgW, *p1A, *p1W, *p2A, *p2W;
    cudaGetSymbolAddress((void**)&abf,  g_Abf);
    cudaGetSymbolAddress((void**)&bbf,  g_Bbf);
    cudaGetSymbolAddress((void**)&mbuf, g_M);
    cudaGetSymbolAddress((void**)&hgA,  g_hgA);
    cudaGetSymbolAddress((void**)&hgW,  g_hgW);
    cudaGetSymbolAddress((void**)&z,    g_Z);
    cudaGetSymbolAddress((void**)&p1A,  g_p1A);
    cudaGetSymbolAddress((void**)&p1W,  g_p1W);
    cudaGetSymbolAddress((void**)&p2A,  g_p2A);
    cudaGetSymbolAddress((void**)&p2W,  g_p2W);
    cudaGetSymbolAddress((void**)&h2,   g_H2);

    cudaFuncSetAttribute(proj_gemm, cudaFuncAttributeMaxDynamicSharedMemorySize, SMEM_REQ);
    cudaFuncSetAttribute(mma_gemm1, cudaFuncAttributeMaxDynamicSharedMemorySize, SMEM_REQ);

    const int CT = 256;
    // zero accumulation target (atomics add into it)
    cudaMemsetAsync(mbuf, 0, (size_t)M_ROWS * PD * sizeof(float));

    // ---- convert inputs to bf16 ----
    auto cvA = [&](const float* src, int doff, int rows) {
        int tot = rows * (FD / 4);
        conv_hi<<<(tot + CT - 1) / CT, CT>>>(src, abf + (size_t)doff * FD, rows);
    };
    cvA(textual, T_OFF,  BSZ);
    cvA(visual,  V_OFF,  BSZ);
    cvA(user,    U_OFF,  BSZ);
    cvA(rtxt,    RT_OFF, BSZ * RNUM);
    cvA(rvis,    RV_OFF, BSZ * RNUM);
    cvA(ruser,   RU_OFF, BSZ * UNUM);

    // ---- convert weights to bf16 (padded) ----
    const float* ws[6] = {txt_w, vis_w, usr_w, rtxt_w, rvis_w, rusr_w};
    for (int i = 0; i < 6; i++) {
        long long tot = (long long)512 * FD;
        conv_hi_pad<<<(unsigned)((tot + CT - 1) / CT), CT>>>(
            ws[i], bbf + (size_t)i * 512 * FD, PD, FD, FD, tot);
    }
    {
        long long tot = (long long)384 * 512;
        conv_hi_pad<<<(unsigned)((tot + CT - 1) / CT), CT>>>(hg_w, hgW, ZD, PD, 512, tot);
        tot = (long long)896 * 2112;
        conv_hi_pad<<<(unsigned)((tot + CT - 1) / CT), CT>>>(p1_w, p1W, 800, 2100, 2112, tot);
        tot = (long long)256 * 832;
        conv_hi_pad<<<(unsigned)((tot + CT - 1) / CT), CT>>>(p2_w, p2W, 200, 800, 832, tot);
    }

    // ---- unified projection GEMM (6 segments, fused tanh + group-sum) ----
    {
        ProjArgs pa;
        pa.A = abf;
        for (int i = 0; i < 6; i++) pa.B[i] = bbf + (size_t)i * 512 * FD;
        pa.bias[0] = txt_b; pa.bias[1] = vis_b; pa.bias[2] = usr_b;
        pa.bias[3] = rtxt_b; pa.bias[4] = rvis_b; pa.bias[5] = rusr_b;
        pa.Mo = mbuf;
        dim3 g(4, 1056);
        proj_gemm<<<g, 256, SMEM_REQ>>>(pa);
    }

    // ---- hg: conv A then GEMM (bias handled in epilogue) ----
    {
        long long tot = (long long)M_PAD_HG * 512;
        conv_hi_pad<<<(unsigned)((tot + CT - 1) / CT), CT>>>(mbuf, hgA, M_ROWS, PD, 512, tot);
        dim3 g(3, M_PAD_HG / 128);
        mma_gemm1<<<g, 256, SMEM_REQ>>>(hgA, hgW, nullptr, z, M_ROWS, ZD, ZD, 512, 0, 0);
    }

    // ---- closed-form hypergraph conv + feat assembly (bf16 out) ----
    epilogue<<<BSZ, 128>>>(z, hg_b, sim, rlabel, lbl_w, lbl_b, p1A);

    // ---- p1: relu, bf16 out into p2A (stride 832) ----
    {
        dim3 g(7, BSZ / 128);
        mma_gemm1<<<g, 256, SMEM_REQ>>>(p1A, p1W, p1_b, p2A, BSZ, 800, 832, 2112, 2, 1);
    }
    // ---- p2: relu, fp32 out ----
    {
        dim3 g(2, BSZ / 128);
        mma_gemm1<<<g, 256, SMEM_REQ>>>(p2A, p2W, p2_b, h2, BSZ, 200, 200, 832, 2, 0);
    }
    // ---- sigmoid head ----
    final_head<<<(BSZ * 32 + 255) / 256, 256>>>(h2, p3_w, p3_b, (float*)d_out);
}